// round 7
// baseline (speedup 1.0000x reference)
#include <cuda_runtime.h>
#include <cuda_fp16.h>

// GravityDecoder, two-phase:
//   K1: zh = fp16(z)  (25.6MB static buffer), m[n] = dot(z[n],W)+b in fp32.
//   K2: per-edge gather of two 256B fp16 rows -> dist2; m_j gathered (4B).
// Rationale: R6 profile showed the kernel pinned at the measured LTS cap
// (~6300 B/cyc). fp16 rows halve the dominant gather bytes.
//
// Inputs: d_in[0]=z f32[N,128], d_in[1]=edge_index i32[2,E],
//         d_in[2]=W f32[128], d_in[3]=b f32 scalar.
// Output: f32 [4,E] = (logits, prob, m_j, dist2).

#define MAX_N 100000
__device__ static uint4 g_zh[MAX_N * 16];   // fp16 z rows: 256 B/row = 16 uint4
__device__ static float g_m[MAX_N];         // m = z@W + b (fp32-exact)

#define WARPS_PER_BLOCK 8
#define THREADS (WARPS_PER_BLOCK * 32)

// ---------------- Kernel 1: convert z to fp16 + precompute m ----------------
__global__ __launch_bounds__(THREADS) void precompute_kernel(
    const float* __restrict__ z,
    const float* __restrict__ W,
    const float* __restrict__ b_ptr,
    int N)
{
    const int lane = threadIdx.x & 31;
    const int row  = (int)((blockIdx.x * (unsigned)blockDim.x + threadIdx.x) >> 5);
    if (row >= N) return;

    const float b = *b_ptr;
    const float4 w4 = reinterpret_cast<const float4*>(W)[lane];
    const float4 v  = reinterpret_cast<const float4*>(z + (size_t)row * 128)[lane];

    // exact fp32 dot
    float mj = v.x * w4.x + v.y * w4.y + v.z * w4.z + v.w * w4.w;
    #pragma unroll
    for (int off = 16; off > 0; off >>= 1)
        mj += __shfl_xor_sync(0xffffffffu, mj, off);

    if (lane == 0) g_m[row] = mj + b;

    // pack this lane's 4 floats as 4 halves (8 B), contiguous layout
    const __half2 lo = __floats2half2_rn(v.x, v.y);
    const __half2 hi = __floats2half2_rn(v.z, v.w);
    uint2 packed;
    packed.x = *reinterpret_cast<const unsigned*>(&lo);
    packed.y = *reinterpret_cast<const unsigned*>(&hi);
    reinterpret_cast<uint2*>(g_zh)[(size_t)row * 32 + lane] = packed;
}

// ---------------- Kernel 2: per-edge distance + outputs ----------------
__device__ __forceinline__ float d2_accum(uint4 A, uint4 C, float acc)
{
    const unsigned* pa = &A.x;
    const unsigned* pc = &C.x;
    #pragma unroll
    for (int k = 0; k < 4; k++) {
        const __half2 ha = *reinterpret_cast<const __half2*>(&pa[k]);
        const __half2 hc = *reinterpret_cast<const __half2*>(&pc[k]);
        const __half2 d  = __hsub2(ha, hc);
        const float2  df = __half22float2(d);
        acc += df.x * df.x + df.y * df.y;
    }
    return acc;
}

__global__ __launch_bounds__(THREADS, 6) void gravity_decoder_kernel(
    const int* __restrict__ edge_index,
    float* __restrict__ out,
    int E)
{
    const int lane   = threadIdx.x & 31;
    const int sub    = lane & 7;        // sublane within 8-lane group
    const int group  = lane >> 3;       // 0..3 : which edge of the 4
    const int warp   = (int)((blockIdx.x * (unsigned)blockDim.x + threadIdx.x) >> 5);
    const int nwarps = (int)((gridDim.x * (unsigned)blockDim.x) >> 5);
    const int stride = nwarps * 4;

    float* __restrict__ out_logits = out;
    float* __restrict__ out_prob   = out + (size_t)E;
    float* __restrict__ out_mj     = out + 2 * (size_t)E;
    float* __restrict__ out_d2     = out + 3 * (size_t)E;

    int e4 = warp * 4;
    if (e4 >= E) return;

    // Prologue: indices for the first iteration
    int e  = e4 + group;
    int es = (e < E) ? e : (E - 1);
    int src = __ldcs(edge_index + es);
    int dst = __ldcs(edge_index + es + (size_t)E);

    for (; e4 < E; e4 += stride) {
        const int  ecur  = e4 + group;
        const bool alive = (ecur < E);

        const uint4* __restrict__ zi = g_zh + (size_t)src * 16;
        const uint4* __restrict__ zj = g_zh + (size_t)dst * 16;

        // 4 gathers in flight per thread (rows are 256 B fp16)
        const uint4 A0 = zi[sub];
        const uint4 A1 = zi[sub + 8];
        const uint4 C0 = zj[sub];
        const uint4 C1 = zj[sub + 8];

        // m_j gather: same address across the 8-lane group -> L1 broadcast
        const float mj = __ldg(g_m + dst);

        // Prefetch next iteration's indices while gathers are in flight
        const int e4n = e4 + stride;
        if (e4n < E) {
            const int en  = e4n + group;
            const int esn = (en < E) ? en : (E - 1);
            src = __ldcs(edge_index + esn);
            dst = __ldcs(edge_index + esn + (size_t)E);
        }

        float d2 = 0.0f;
        d2 = d2_accum(A0, C0, d2);
        d2 = d2_accum(A1, C1, d2);

        // 3-step butterfly within each 8-lane group
        #pragma unroll
        for (int off = 4; off > 0; off >>= 1)
            d2 += __shfl_xor_sync(0xffffffffu, d2, off);

        d2 += 1e-7f;
        const float logit = mj - __logf(d2);

        if (alive) {
            if (sub == 0)      __stcs(out_logits + ecur, logit);
            else if (sub == 1) __stcs(out_prob + ecur, __fdividef(1.0f, 1.0f + __expf(-logit)));
            else if (sub == 2) __stcs(out_mj + ecur, mj);
            else if (sub == 3) __stcs(out_d2 + ecur, d2);
        }
    }
}

extern "C" void kernel_launch(void* const* d_in, const int* in_sizes, int n_in,
                              void* d_out, int out_size)
{
    const float* z   = (const float*)d_in[0];
    const int*   ei  = (const int*)d_in[1];
    const float* W   = (const float*)d_in[2];
    const float* b   = (const float*)d_in[3];
    float*       out = (float*)d_out;

    const int N = in_sizes[0] / 128;
    const int E = in_sizes[1] / 2;

    // K1: one warp per node row
    int blocks1 = (N + WARPS_PER_BLOCK - 1) / WARPS_PER_BLOCK;
    precompute_kernel<<<blocks1, THREADS>>>(z, W, b, N);

    // K2: 4 edges per warp, grid-stride
    int blocks2 = (E + WARPS_PER_BLOCK * 4 - 1) / (WARPS_PER_BLOCK * 4);
    if (blocks2 > 4736) blocks2 = 4736;
    gravity_decoder_kernel<<<blocks2, THREADS>>>(ei, out, E);
}

// round 8
// speedup vs baseline: 1.1304x; 1.1304x over previous
#include <cuda_runtime.h>
#include <cuda_fp16.h>

// GravityDecoder, two-phase:
//   K1: zh = fp16(z) (25.6MB static buffer), m[n] = dot(z[n],W)+b in fp32.
//   K2: per-edge gather of two 256B fp16 rows -> dist2; m_j gathered (4B).
// K2 layout: 4 lanes per edge, 8 edges per warp -> 8 uint4 gathers in flight
// per thread (restores R4's winning MLP shape on half the bytes).

#define MAX_N 100000
__device__ static uint4 g_zh[MAX_N * 16];   // fp16 z rows: 256 B/row = 16 uint4
__device__ static float g_m[MAX_N];         // m = z@W + b (fp32-exact)

#define WARPS_PER_BLOCK 8
#define THREADS (WARPS_PER_BLOCK * 32)

// ---------------- Kernel 1: convert z to fp16 + precompute m ----------------
__global__ __launch_bounds__(THREADS) void precompute_kernel(
    const float* __restrict__ z,
    const float* __restrict__ W,
    const float* __restrict__ b_ptr,
    int N)
{
    const int lane = threadIdx.x & 31;
    const int row  = (int)((blockIdx.x * (unsigned)blockDim.x + threadIdx.x) >> 5);
    if (row >= N) return;

    const float b = *b_ptr;
    const float4 w4 = reinterpret_cast<const float4*>(W)[lane];
    const float4 v  = reinterpret_cast<const float4*>(z + (size_t)row * 128)[lane];

    // exact fp32 dot
    float mj = v.x * w4.x + v.y * w4.y + v.z * w4.z + v.w * w4.w;
    #pragma unroll
    for (int off = 16; off > 0; off >>= 1)
        mj += __shfl_xor_sync(0xffffffffu, mj, off);

    if (lane == 0) g_m[row] = mj + b;

    // pack this lane's 4 floats as 4 halves (8 B), contiguous layout
    const __half2 lo = __floats2half2_rn(v.x, v.y);
    const __half2 hi = __floats2half2_rn(v.z, v.w);
    uint2 packed;
    packed.x = *reinterpret_cast<const unsigned*>(&lo);
    packed.y = *reinterpret_cast<const unsigned*>(&hi);
    reinterpret_cast<uint2*>(g_zh)[(size_t)row * 32 + lane] = packed;
}

// ---------------- Kernel 2: per-edge distance + outputs ----------------
__device__ __forceinline__ float d2_accum(uint4 A, uint4 C, float acc)
{
    const unsigned* pa = &A.x;
    const unsigned* pc = &C.x;
    #pragma unroll
    for (int k = 0; k < 4; k++) {
        const __half2 ha = *reinterpret_cast<const __half2*>(&pa[k]);
        const __half2 hc = *reinterpret_cast<const __half2*>(&pc[k]);
        const __half2 d  = __hsub2(ha, hc);
        const float2  df = __half22float2(d);
        acc += df.x * df.x + df.y * df.y;
    }
    return acc;
}

__global__ __launch_bounds__(THREADS, 5) void gravity_decoder_kernel(
    const int* __restrict__ edge_index,
    float* __restrict__ out,
    int E)
{
    const int lane   = threadIdx.x & 31;
    const int sub    = lane & 3;        // sublane within 4-lane group
    const int group  = lane >> 2;       // 0..7 : which edge of the 8
    const int warp   = (int)((blockIdx.x * (unsigned)blockDim.x + threadIdx.x) >> 5);
    const int nwarps = (int)((gridDim.x * (unsigned)blockDim.x) >> 5);
    const int stride = nwarps * 8;

    float* __restrict__ out_logits = out;
    float* __restrict__ out_prob   = out + (size_t)E;
    float* __restrict__ out_mj     = out + 2 * (size_t)E;
    float* __restrict__ out_d2     = out + 3 * (size_t)E;

    int e8 = warp * 8;
    if (e8 >= E) return;

    // Prologue: indices for the first iteration
    {
        const int e  = e8 + group;
        const int es = (e < E) ? e : (E - 1);
        // loads below
    }
    int e  = e8 + group;
    int es = (e < E) ? e : (E - 1);
    int src = __ldcs(edge_index + es);
    int dst = __ldcs(edge_index + es + (size_t)E);

    for (; e8 < E; e8 += stride) {
        const int  ecur  = e8 + group;
        const bool alive = (ecur < E);

        const uint4* __restrict__ zi = g_zh + (size_t)src * 16;
        const uint4* __restrict__ zj = g_zh + (size_t)dst * 16;

        // 8 gathers in flight per thread: 4 lanes x 4 uint4 cover a 256B row
        const uint4 A0 = zi[sub];
        const uint4 A1 = zi[sub + 4];
        const uint4 A2 = zi[sub + 8];
        const uint4 A3 = zi[sub + 12];
        const uint4 C0 = zj[sub];
        const uint4 C1 = zj[sub + 4];
        const uint4 C2 = zj[sub + 8];
        const uint4 C3 = zj[sub + 12];

        // m_j: same address across the 4-lane group -> broadcast
        const float mj = __ldg(g_m + dst);

        // Prefetch next iteration's indices while gathers are in flight
        const int e8n = e8 + stride;
        if (e8n < E) {
            const int en  = e8n + group;
            const int esn = (en < E) ? en : (E - 1);
            src = __ldcs(edge_index + esn);
            dst = __ldcs(edge_index + esn + (size_t)E);
        }

        float d2 = 0.0f;
        d2 = d2_accum(A0, C0, d2);
        d2 = d2_accum(A1, C1, d2);
        d2 = d2_accum(A2, C2, d2);
        d2 = d2_accum(A3, C3, d2);

        // 2-step butterfly within each 4-lane group
        #pragma unroll
        for (int off = 2; off > 0; off >>= 1)
            d2 += __shfl_xor_sync(0xffffffffu, d2, off);

        d2 += 1e-7f;
        const float logit = mj - __logf(d2);

        if (alive) {
            if (sub == 0)      __stcs(out_logits + ecur, logit);
            else if (sub == 1) __stcs(out_prob + ecur, __fdividef(1.0f, 1.0f + __expf(-logit)));
            else if (sub == 2) __stcs(out_mj + ecur, mj);
            else               __stcs(out_d2 + ecur, d2);
        }
    }
}

extern "C" void kernel_launch(void* const* d_in, const int* in_sizes, int n_in,
                              void* d_out, int out_size)
{
    const float* z   = (const float*)d_in[0];
    const int*   ei  = (const int*)d_in[1];
    const float* W   = (const float*)d_in[2];
    const float* b   = (const float*)d_in[3];
    float*       out = (float*)d_out;

    const int N = in_sizes[0] / 128;
    const int E = in_sizes[1] / 2;

    // K1: one warp per node row
    int blocks1 = (N + WARPS_PER_BLOCK - 1) / WARPS_PER_BLOCK;
    precompute_kernel<<<blocks1, THREADS>>>(z, W, b, N);

    // K2: 8 edges per warp, grid-stride
    int blocks2 = (E + WARPS_PER_BLOCK * 8 - 1) / (WARPS_PER_BLOCK * 8);
    if (blocks2 > 4736) blocks2 = 4736;
    gravity_decoder_kernel<<<blocks2, THREADS>>>(ei, out, E);
}

// round 9
// speedup vs baseline: 1.1964x; 1.0584x over previous
#include <cuda_runtime.h>
#include <cuda_fp16.h>

// GravityDecoder, two-phase with PDL overlap:
//   K1: zh = fp16(z) (25.6MB static), m[n] = dot(z[n],W)+b fp32. Persistent
//       grid-stride with next-row prefetch.
//   K2: per-edge gather of two 256B fp16 rows -> dist2; m_j gathered.
//       Launched with programmatic dependent launch: prologue index loads
//       run before cudaGridDependencySynchronize() (they don't depend on K1).

#define MAX_N 100000
__device__ static uint4 g_zh[MAX_N * 16];   // fp16 z rows: 256 B/row
__device__ static float g_m[MAX_N];         // m = z@W + b

#define WARPS_PER_BLOCK 8
#define THREADS (WARPS_PER_BLOCK * 32)

// ---------------- Kernel 1: convert z to fp16 + precompute m ----------------
__global__ __launch_bounds__(THREADS) void precompute_kernel(
    const float* __restrict__ z,
    const float* __restrict__ W,
    const float* __restrict__ b_ptr,
    int N)
{
    const int lane   = threadIdx.x & 31;
    const int warp   = (int)((blockIdx.x * (unsigned)blockDim.x + threadIdx.x) >> 5);
    const int nwarps = (int)((gridDim.x * (unsigned)blockDim.x) >> 5);

    const float b = *b_ptr;
    const float4 w4 = reinterpret_cast<const float4*>(W)[lane];

    int row = warp;
    if (row < N) {
        float4 v = reinterpret_cast<const float4*>(z + (size_t)row * 128)[lane];
        for (; row < N; ) {
            const int next = row + nwarps;
            float4 vn;
            if (next < N)   // prefetch next row while reducing current
                vn = reinterpret_cast<const float4*>(z + (size_t)next * 128)[lane];

            float mj = v.x * w4.x + v.y * w4.y + v.z * w4.z + v.w * w4.w;
            #pragma unroll
            for (int off = 16; off > 0; off >>= 1)
                mj += __shfl_xor_sync(0xffffffffu, mj, off);
            if (lane == 0) g_m[row] = mj + b;

            const __half2 lo = __floats2half2_rn(v.x, v.y);
            const __half2 hi = __floats2half2_rn(v.z, v.w);
            uint2 packed;
            packed.x = *reinterpret_cast<const unsigned*>(&lo);
            packed.y = *reinterpret_cast<const unsigned*>(&hi);
            reinterpret_cast<uint2*>(g_zh)[(size_t)row * 32 + lane] = packed;

            row = next;
            v   = vn;
        }
    }

    // Allow the dependent kernel (K2) to launch; its gather phase still waits
    // on full grid completion via cudaGridDependencySynchronize().
    cudaTriggerProgrammaticLaunchCompletion();
}

// ---------------- Kernel 2: per-edge distance + outputs ----------------
__device__ __forceinline__ float d2_accum(uint4 A, uint4 C, float acc)
{
    const unsigned* pa = &A.x;
    const unsigned* pc = &C.x;
    #pragma unroll
    for (int k = 0; k < 4; k++) {
        const __half2 ha = *reinterpret_cast<const __half2*>(&pa[k]);
        const __half2 hc = *reinterpret_cast<const __half2*>(&pc[k]);
        const __half2 d  = __hsub2(ha, hc);
        const float2  df = __half22float2(d);
        acc += df.x * df.x + df.y * df.y;
    }
    return acc;
}

__global__ __launch_bounds__(THREADS, 5) void gravity_decoder_kernel(
    const int* __restrict__ edge_index,
    float* __restrict__ out,
    int E)
{
    const int lane   = threadIdx.x & 31;
    const int sub    = lane & 3;        // sublane within 4-lane group
    const int group  = lane >> 2;       // 0..7 : which edge of the 8
    const int warp   = (int)((blockIdx.x * (unsigned)blockDim.x + threadIdx.x) >> 5);
    const int nwarps = (int)((gridDim.x * (unsigned)blockDim.x) >> 5);
    const int stride = nwarps * 8;

    float* __restrict__ out_logits = out;
    float* __restrict__ out_prob   = out + (size_t)E;
    float* __restrict__ out_mj     = out + 2 * (size_t)E;
    float* __restrict__ out_d2     = out + 3 * (size_t)E;

    int e8 = warp * 8;
    if (e8 >= E) {
        cudaGridDependencySynchronize();
        return;
    }

    // Prologue: index loads are independent of K1 -> issue before the
    // grid dependency sync so they overlap K1's tail.
    int e  = e8 + group;
    int es = (e < E) ? e : (E - 1);
    int src = __ldcs(edge_index + es);
    int dst = __ldcs(edge_index + es + (size_t)E);

    cudaGridDependencySynchronize();   // g_zh / g_m valid after this

    for (; e8 < E; e8 += stride) {
        const int  ecur  = e8 + group;
        const bool alive = (ecur < E);

        const uint4* __restrict__ zi = g_zh + (size_t)src * 16;
        const uint4* __restrict__ zj = g_zh + (size_t)dst * 16;

        // 8 gathers in flight per thread: 4 lanes x 4 uint4 cover a 256B row
        const uint4 A0 = zi[sub];
        const uint4 A1 = zi[sub + 4];
        const uint4 A2 = zi[sub + 8];
        const uint4 A3 = zi[sub + 12];
        const uint4 C0 = zj[sub];
        const uint4 C1 = zj[sub + 4];
        const uint4 C2 = zj[sub + 8];
        const uint4 C3 = zj[sub + 12];

        // m_j: same address across the 4-lane group -> broadcast
        const float mj = __ldg(g_m + dst);

        // Prefetch next iteration's indices while gathers are in flight
        const int e8n = e8 + stride;
        if (e8n < E) {
            const int en  = e8n + group;
            const int esn = (en < E) ? en : (E - 1);
            src = __ldcs(edge_index + esn);
            dst = __ldcs(edge_index + esn + (size_t)E);
        }

        float d2 = 0.0f;
        d2 = d2_accum(A0, C0, d2);
        d2 = d2_accum(A1, C1, d2);
        d2 = d2_accum(A2, C2, d2);
        d2 = d2_accum(A3, C3, d2);

        // 2-step butterfly within each 4-lane group
        #pragma unroll
        for (int off = 2; off > 0; off >>= 1)
            d2 += __shfl_xor_sync(0xffffffffu, d2, off);

        d2 += 1e-7f;
        const float logit = mj - __logf(d2);

        if (alive) {
            if (sub == 0)      __stcs(out_logits + ecur, logit);
            else if (sub == 1) __stcs(out_prob + ecur, __fdividef(1.0f, 1.0f + __expf(-logit)));
            else if (sub == 2) __stcs(out_mj + ecur, mj);
            else               __stcs(out_d2 + ecur, d2);
        }
    }
}

extern "C" void kernel_launch(void* const* d_in, const int* in_sizes, int n_in,
                              void* d_out, int out_size)
{
    const float* z   = (const float*)d_in[0];
    const int*   ei  = (const int*)d_in[1];
    const float* W   = (const float*)d_in[2];
    const float* b   = (const float*)d_in[3];
    float*       out = (float*)d_out;

    const int N = in_sizes[0] / 128;
    const int E = in_sizes[1] / 2;

    // K1: persistent grid-stride, ~1480 blocks
    int blocks1 = (N + WARPS_PER_BLOCK - 1) / WARPS_PER_BLOCK;
    if (blocks1 > 1480) blocks1 = 1480;
    precompute_kernel<<<blocks1, THREADS>>>(z, W, b, N);

    // K2: 8 edges per warp, grid-stride, launched with PDL so its index
    // prologue overlaps K1's tail.
    int blocks2 = (E + WARPS_PER_BLOCK * 8 - 1) / (WARPS_PER_BLOCK * 8);
    if (blocks2 > 4736) blocks2 = 4736;

    cudaLaunchConfig_t cfg = {};
    cfg.gridDim  = dim3((unsigned)blocks2, 1, 1);
    cfg.blockDim = dim3(THREADS, 1, 1);
    cfg.dynamicSmemBytes = 0;
    cfg.stream = 0;
    cudaLaunchAttribute attrs[1];
    attrs[0].id = cudaLaunchAttributeProgrammaticStreamSerialization;
    attrs[0].val.programmaticStreamSerializationAllowed = 1;
    cfg.attrs = attrs;
    cfg.numAttrs = 1;
    cudaLaunchKernelEx(&cfg, gravity_decoder_kernel, ei, out, E);
}